// round 1
// baseline (speedup 1.0000x reference)
#include <cuda_runtime.h>

// q = prod_i cos(pi/2 + 2*x_i) = prod_i (-sin(2*x_i)) = prod_i sin(2*x_i)  (8 factors, signs cancel)
// out[i] = { scale*q, -scale*q }

__global__ void __launch_bounds__(256) qnn_kernel(
    const float4* __restrict__ x,      // [B, 8] viewed as [B*2] float4
    const float* __restrict__ scale,   // scalar on device
    float2* __restrict__ out,          // [B] pairs
    int B)
{
    int i = blockIdx.x * blockDim.x + threadIdx.x;
    if (i >= B) return;

    float4 a = x[2 * i + 0];
    float4 b = x[2 * i + 1];

    float q = __sinf(2.0f * a.x);
    q *= __sinf(2.0f * a.y);
    q *= __sinf(2.0f * a.z);
    q *= __sinf(2.0f * a.w);
    q *= __sinf(2.0f * b.x);
    q *= __sinf(2.0f * b.y);
    q *= __sinf(2.0f * b.z);
    q *= __sinf(2.0f * b.w);

    float s = __ldg(scale);
    out[i] = make_float2(s * q, -s * q);
}

extern "C" void kernel_launch(void* const* d_in, const int* in_sizes, int n_in,
                              void* d_out, int out_size)
{
    const float* x     = (const float*)d_in[0];   // [B, 8]
    // d_in[1] = weights (unused by the circuit, n_layers = 0)
    const float* scale = (const float*)d_in[2];   // scalar

    int B = in_sizes[0] / 8;
    float2* out = (float2*)d_out;

    int threads = 256;
    int blocks = (B + threads - 1) / threads;
    qnn_kernel<<<blocks, threads>>>((const float4*)x, scale, out, B);
}